// round 1
// baseline (speedup 1.0000x reference)
#include <cuda_runtime.h>
#include <cstdint>

typedef unsigned long long ull;

// ---------------------------------------------------------------------------
// Packed f32x2 helpers (sm_100+): 2 fp32 FMAs per instruction.
// ---------------------------------------------------------------------------
__device__ __forceinline__ ull pack2(float lo, float hi) {
    ull r; asm("mov.b64 %0, {%1, %2};" : "=l"(r) : "f"(lo), "f"(hi)); return r;
}
__device__ __forceinline__ void unpack2(ull v, float& lo, float& hi) {
    asm("mov.b64 {%0, %1}, %2;" : "=f"(lo), "=f"(hi) : "l"(v));
}
#define FMA2(acc, a, b) asm("fma.rn.f32x2 %0, %1, %2, %0;" : "+l"(acc) : "l"(a), "l"(b))

__device__ __forceinline__ float sigf(float x) { return 1.f / (1.f + __expf(-x)); }
__device__ __forceinline__ float tanh_fast(float x) {
    // tanh(x) = 1 - 2/(exp(2x)+1); robust at +-inf, abs err ~1e-7 near 0.
    return 1.f - 2.f / (__expf(2.f * x) + 1.f);
}

// Scratch: P[v][j] = sum_d emb[v,d]*w_ih0[j,d] + b_ih0[j] + b_hh0[j]
// V=50000, 4H=256 -> 51.2 MB static device array (no dynamic alloc allowed).
__device__ float g_P[50000 * 256];

// ---------------------------------------------------------------------------
// Kernel 1: per-vocab input transform. Thread j owns w_ih0 row j in registers
// (E=100 floats = 50 packed pairs). Each iteration: 4 vocab rows staged in
// shared, 4 independent 50-FMA2 chains per thread for ILP.
// ---------------------------------------------------------------------------
__global__ __launch_bounds__(256)
void prep_kernel(const float* __restrict__ emb,
                 const float* __restrict__ w_ih0,
                 const float* __restrict__ b_ih0,
                 const float* __restrict__ b_hh0,
                 int V)
{
    const int E = 100;
    const int j = threadIdx.x;

    ull w[50];
    {
        const ull* wp = reinterpret_cast<const ull*>(w_ih0 + (size_t)j * E);
#pragma unroll
        for (int k = 0; k < 50; k++) w[k] = wp[k];
    }
    const float bias = b_ih0[j] + b_hh0[j];

    __shared__ __align__(16) float es[4 * 100];

    for (int v0 = blockIdx.x * 4; v0 < V; v0 += gridDim.x * 4) {
        __syncthreads();                       // prior readers done with es
        int nload = min(4 * E, (V - v0) * E);  // rows are contiguous in gmem
        for (int idx = j; idx < nload; idx += 256) es[idx] = emb[(size_t)v0 * E + idx];
        __syncthreads();

        ull acc0 = 0, acc1 = 0, acc2 = 0, acc3 = 0;
#pragma unroll
        for (int q = 0; q < 25; q++) {
            ulonglong2 h0 = *reinterpret_cast<const ulonglong2*>(&es[0 * 100 + q * 4]);
            ulonglong2 h1 = *reinterpret_cast<const ulonglong2*>(&es[1 * 100 + q * 4]);
            ulonglong2 h2 = *reinterpret_cast<const ulonglong2*>(&es[2 * 100 + q * 4]);
            ulonglong2 h3 = *reinterpret_cast<const ulonglong2*>(&es[3 * 100 + q * 4]);
            FMA2(acc0, w[2 * q], h0.x);  FMA2(acc0, w[2 * q + 1], h0.y);
            FMA2(acc1, w[2 * q], h1.x);  FMA2(acc1, w[2 * q + 1], h1.y);
            FMA2(acc2, w[2 * q], h2.x);  FMA2(acc2, w[2 * q + 1], h2.y);
            FMA2(acc3, w[2 * q], h3.x);  FMA2(acc3, w[2 * q + 1], h3.y);
        }
        ull accs[4] = {acc0, acc1, acc2, acc3};
#pragma unroll
        for (int r = 0; r < 4; r++) {
            if (v0 + r < V) {
                float lo, hi; unpack2(accs[r], lo, hi);
                g_P[(size_t)(v0 + r) * 256 + j] = lo + hi + bias;
            }
        }
    }
}

// ---------------------------------------------------------------------------
// Kernel 2: fused 2-layer LSTM scan + final FC. One CTA = 2 batch rows,
// 256 threads; thread j owns gate-row j of w_hh0, w_ih1, w_hh1 in registers.
// Per step: gather P row (prefetched 1 step ahead), layer0 matvec + layer1
// recurrent matvec (phase a), layer0 cell (threads 0..127, phase b),
// layer1 input matvec (phase c), layer1 cell (threads 128..255, phase d).
// ---------------------------------------------------------------------------
__global__ __launch_bounds__(256, 1)
void scan_kernel(const int*   __restrict__ x,
                 const float* __restrict__ w_hh0,
                 const float* __restrict__ w_ih1,
                 const float* __restrict__ w_hh1,
                 const float* __restrict__ b_ih1,
                 const float* __restrict__ b_hh1,
                 const float* __restrict__ fc_w,
                 const float* __restrict__ fc_b,
                 float* __restrict__ out,
                 int T)
{
    const int HH = 64, GG = 256;
    const int j  = threadIdx.x;
    const int b0 = blockIdx.x * 2;

    __shared__ __align__(16) float h0s[2][HH];
    __shared__ __align__(16) float h1s[2][HH];
    __shared__ float sg0[2][GG];
    __shared__ float sg1[2][GG];

    ull w0[32], wi[32], wh[32];
    {
        const ull* p = reinterpret_cast<const ull*>(w_hh0 + (size_t)j * HH);
#pragma unroll
        for (int k = 0; k < 32; k++) w0[k] = p[k];
        p = reinterpret_cast<const ull*>(w_ih1 + (size_t)j * HH);
#pragma unroll
        for (int k = 0; k < 32; k++) wi[k] = p[k];
        p = reinterpret_cast<const ull*>(w_hh1 + (size_t)j * HH);
#pragma unroll
        for (int k = 0; k < 32; k++) wh[k] = p[k];
    }
    const float bias1 = b_ih1[j] + b_hh1[j];

    if (j < HH) {
        h0s[0][j] = 0.f; h0s[1][j] = 0.f;
        h1s[0][j] = 0.f; h1s[1][j] = 0.f;
    }
    float cst = 0.f;  // per-thread cell state: t<128 -> layer0, t>=128 -> layer1

    const int* xb0 = x + (size_t)b0 * T;
    const int* xb1 = x + (size_t)(b0 + 1) * T;
    float curP0 = g_P[(size_t)xb0[0] * GG + j];
    float curP1 = g_P[(size_t)xb1[0] * GG + j];
    __syncthreads();

    for (int t = 0; t < T; t++) {
        // Prefetch next step's P rows (in flight across this step's compute).
        int tn = min(t + 1, T - 1);
        float nP0 = g_P[(size_t)xb0[tn] * GG + j];
        float nP1 = g_P[(size_t)xb1[tn] * GG + j];

        // ---- phase a: g0 = P + h0.w_hh0 ; g1 partial = bias1 + h1.w_hh1 ----
        ull a0  = pack2(curP0, 0.f);
        ull a1  = pack2(curP1, 0.f);
        ull g1a = pack2(bias1, 0.f);
        ull g1b = 0;  // bias1 added at store
#pragma unroll
        for (int q = 0; q < 16; q++) {
            ulonglong2 hv0 = *reinterpret_cast<const ulonglong2*>(&h0s[0][q * 4]);
            ulonglong2 hv1 = *reinterpret_cast<const ulonglong2*>(&h0s[1][q * 4]);
            FMA2(a0, w0[2 * q],     hv0.x);
            FMA2(a0, w0[2 * q + 1], hv0.y);
            FMA2(a1, w0[2 * q],     hv1.x);
            FMA2(a1, w0[2 * q + 1], hv1.y);
        }
#pragma unroll
        for (int q = 0; q < 16; q++) {
            ulonglong2 hv0 = *reinterpret_cast<const ulonglong2*>(&h1s[0][q * 4]);
            ulonglong2 hv1 = *reinterpret_cast<const ulonglong2*>(&h1s[1][q * 4]);
            FMA2(g1a, wh[2 * q],     hv0.x);
            FMA2(g1a, wh[2 * q + 1], hv0.y);
            FMA2(g1b, wh[2 * q],     hv1.x);
            FMA2(g1b, wh[2 * q + 1], hv1.y);
        }
        {
            float lo, hi;
            unpack2(a0, lo, hi); sg0[0][j] = lo + hi;
            unpack2(a1, lo, hi); sg0[1][j] = lo + hi;
        }
        __syncthreads();

        // ---- phase b: layer0 LSTM cell on threads 0..127 ----
        if (j < 128) {
            int b = j >> 6, u = j & 63;
            float gi = sg0[b][u], gf = sg0[b][u + 64];
            float gz = sg0[b][u + 128], go = sg0[b][u + 192];
            float iv = sigf(gi), fv = sigf(gf), zv = tanh_fast(gz), ov = sigf(go);
            cst = fv * cst + iv * zv;
            h0s[b][u] = ov * tanh_fast(cst);
        }
        __syncthreads();

        // ---- phase c: g1 += h0_new . w_ih1 ----
#pragma unroll
        for (int q = 0; q < 16; q++) {
            ulonglong2 hv0 = *reinterpret_cast<const ulonglong2*>(&h0s[0][q * 4]);
            ulonglong2 hv1 = *reinterpret_cast<const ulonglong2*>(&h0s[1][q * 4]);
            FMA2(g1a, wi[2 * q],     hv0.x);
            FMA2(g1a, wi[2 * q + 1], hv0.y);
            FMA2(g1b, wi[2 * q],     hv1.x);
            FMA2(g1b, wi[2 * q + 1], hv1.y);
        }
        {
            float lo, hi;
            unpack2(g1a, lo, hi); sg1[0][j] = lo + hi;
            unpack2(g1b, lo, hi); sg1[1][j] = lo + hi + bias1;
        }
        __syncthreads();

        // ---- phase d: layer1 LSTM cell on threads 128..255 ----
        if (j >= 128) {
            int b = (j >> 6) & 1, u = j & 63;
            float gi = sg1[b][u], gf = sg1[b][u + 64];
            float gz = sg1[b][u + 128], go = sg1[b][u + 192];
            float iv = sigf(gi), fv = sigf(gf), zv = tanh_fast(gz), ov = sigf(go);
            cst = fv * cst + iv * zv;
            h1s[b][u] = ov * tanh_fast(cst);
        }
        curP0 = nP0; curP1 = nP1;
        __syncthreads();
    }

    // ---- final: out[b] = sigmoid(relu(h1_last) . fc_w + fc_b) ----
    if (j < 2) {
        float s = fc_b[0];
#pragma unroll
        for (int u = 0; u < HH; u++)
            s += fmaxf(h1s[j][u], 0.f) * fc_w[u];
        out[b0 + j] = sigf(s);
    }
}

// ---------------------------------------------------------------------------
// Launch
// ---------------------------------------------------------------------------
extern "C" void kernel_launch(void* const* d_in, const int* in_sizes, int n_in,
                              void* d_out, int out_size)
{
    const int*   x     = (const int*)  d_in[0];
    const float* emb   = (const float*)d_in[1];
    const float* w_ih0 = (const float*)d_in[2];
    const float* w_hh0 = (const float*)d_in[3];
    const float* b_ih0 = (const float*)d_in[4];
    const float* b_hh0 = (const float*)d_in[5];
    const float* w_ih1 = (const float*)d_in[6];
    const float* w_hh1 = (const float*)d_in[7];
    const float* b_ih1 = (const float*)d_in[8];
    const float* b_hh1 = (const float*)d_in[9];
    const float* fc_w  = (const float*)d_in[10];
    const float* fc_b  = (const float*)d_in[11];
    float* out = (float*)d_out;

    const int B = out_size;              // 256
    const int T = in_sizes[0] / B;       // 512
    const int E = in_sizes[2] / 256;     // 100
    const int V = in_sizes[1] / E;       // 50000

    (void)n_in; (void)E;

    prep_kernel<<<296, 256>>>(emb, w_ih0, b_ih0, b_hh0, V);
    scan_kernel<<<B / 2, 256>>>(x, w_hh0, w_ih1, w_hh1, b_ih1, b_hh1,
                                fc_w, fc_b, out, T);
}